// round 11
// baseline (speedup 1.0000x reference)
#include <cuda_runtime.h>
#include <cuda_fp16.h>
#include <cstdint>

// Problem dims (fixed)
#define BB 4
#define TT 4096
#define EE 1024
#define HH 64
#define BT (BB * TT)          // 16384 rows
#define SCALE 0.03125f        // E^-0.5

// Scratch (device globals)
__device__ float g_M[BB * HH * HH];          // per-batch K^T V (fp32)
__device__ float g_c[BB * HH];               // per-batch scale*(bq @ M)
__device__ __half g_WT[128 * EE];            // [n][k]; n: k 0-63, v 64-127
__device__ __half g_Wp[BB * HH * EE];        // W'' transposed [b][n][k] fp16

// ---------------------------------------------------------------------------
// PTX helpers (baseline PTX, valid under compute_103)
// ---------------------------------------------------------------------------
#define MMA_FP16(c, a, b)                                                     \
    asm volatile(                                                             \
        "mma.sync.aligned.m16n8k16.row.col.f32.f16.f16.f32 "                  \
        "{%0,%1,%2,%3}, {%4,%5,%6,%7}, {%8,%9}, {%0,%1,%2,%3};\n"             \
        : "+f"(c[0]), "+f"(c[1]), "+f"(c[2]), "+f"(c[3])                      \
        : "r"(a[0]), "r"(a[1]), "r"(a[2]), "r"(a[3]), "r"(b[0]), "r"(b[1]))

#define LDSM4(r0, r1, r2, r3, addr)                                           \
    asm volatile("ldmatrix.sync.aligned.m8n8.x4.shared.b16 {%0,%1,%2,%3}, [%4];" \
        : "=r"(r0), "=r"(r1), "=r"(r2), "=r"(r3) : "r"(addr))

#define CP_ASYNC16(dst, src) \
    asm volatile("cp.async.cg.shared.global [%0], [%1], 16;" :: "r"(dst), "l"(src))
#define CP_COMMIT() asm volatile("cp.async.commit_group;")
#define CP_WAIT0()  asm volatile("cp.async.wait_group 0;")

__device__ __forceinline__ uint32_t smem_u32(const void* p) {
    uint32_t a;
    asm("{ .reg .u64 t; cvta.to.shared.u64 t, %1; cvt.u32.u64 %0, t; }" : "=r"(a) : "l"(p));
    return a;
}

// ---------------------------------------------------------------------------
// Prep: zero g_M + convert Wk|Wv (fp32 [k][n]) -> fp16 transposed [n][k]
// ---------------------------------------------------------------------------
__global__ void prep_kernel(const float* __restrict__ Wk,
                            const float* __restrict__ Wv)
{
    int i = blockIdx.x * blockDim.x + threadIdx.x;
    if (i < BB * HH * HH) g_M[i] = 0.f;
    if (i >= 128 * EE) return;
    int n = i % 128;
    int k = i / 128;
    const float* W = (n < 64) ? Wk : Wv;
    g_WT[(size_t)n * EE + k] = __float2half_rn(W[k * HH + (n & 63)]);
}

// ---------------------------------------------------------------------------
// kv kernel: block = 64 rows x 128 cols (K|V), fp16 single-pass HMMA,
// epilogue folds partial K^T V into g_M via atomics. No g_K/g_V. grid=256.
// 8 warps (2M x 4N), warp tile 32x32. BK=32.
// Dynamic smem: mainloop 2 x (Xh 5120 + Wh 10240) = 30720;
// epilogue reuses pool as Ks[64][68] (17408) + Vs (17408) = 34816.
// ---------------------------------------------------------------------------
#define KV_BUFS 15360
#define KV_SMEM 34816

__global__ __launch_bounds__(256) void kv_mma_kernel(
    const float* __restrict__ X,
    const float* __restrict__ bk,
    const float* __restrict__ bv)
{
    extern __shared__ __align__(16) char sm[];
    const uint32_t sb = smem_u32(sm);
    const int t    = threadIdx.x;
    const int warp = t >> 5;
    const int lane = t & 31;
    const int g    = lane >> 2;
    const int tig  = lane & 3;
    const int wm   = warp >> 2;      // 0..1 -> m offset 32*wm
    const int wn   = warp & 3;       // 0..3 -> n offset 32*wn
    const int m0   = blockIdx.x * 64;
    const int batch = m0 >> 12;

    const float4* X4 = (const float4*)X;

    float c[2][4][4];
#pragma unroll
    for (int mt = 0; mt < 2; mt++)
#pragma unroll
        for (int nt = 0; nt < 4; nt++)
#pragma unroll
            for (int j = 0; j < 4; j++) c[mt][nt][j] = 0.f;

    float4 xr[2];
    const int xrow = t >> 2;         // 0..63
    const int xc4  = (t & 3) * 2;

    auto ldgX = [&](int k0) {
#pragma unroll
        for (int j = 0; j < 2; j++)
            xr[j] = X4[(size_t)(m0 + xrow) * (EE / 4) + (k0 >> 2) + xc4 + j];
    };
    auto stX = [&](int buf) {
        char* xh = sm + buf * KV_BUFS;
#pragma unroll
        for (int j = 0; j < 2; j++) {
            __half2 p0 = __floats2half2_rn(xr[j].x, xr[j].y);
            __half2 p1 = __floats2half2_rn(xr[j].z, xr[j].w);
            int off = xrow * 80 + (xc4 + j) * 8;
            *(uint2*)(xh + off) = make_uint2(*(uint32_t*)&p0, *(uint32_t*)&p1);
        }
    };
    // W tile: 128 rows x 32 cols fp16 = 512 x 16B, 2/thread
    auto cpW = [&](int k0, int buf) {
        uint32_t wbase = sb + buf * KV_BUFS + 5120;
#pragma unroll
        for (int j = 0; j < 2; j++) {
            int cc = t + j * 256;          // 0..511
            int row = cc >> 2;             // 0..127
            int q = cc & 3;
            const __half* src = g_WT + (size_t)row * EE + k0 + q * 8;
            uint32_t dst = wbase + row * 80 + q * 16;
            CP_ASYNC16(dst, src);
        }
    };
    auto domma = [&](int buf) {
        uint32_t xh = sb + buf * KV_BUFS;
#pragma unroll
        for (int ks = 0; ks < 2; ks++) {
            const int kboff = ks * 32;
            uint32_t a[2][4], bh[4][2];
#pragma unroll
            for (int mt = 0; mt < 2; mt++) {
                uint32_t addr = xh + (uint32_t)((wm * 32 + mt * 16 + (lane & 15)) * 80
                                                + kboff + (lane >> 4) * 16);
                LDSM4(a[mt][0], a[mt][1], a[mt][2], a[mt][3], addr);
            }
#pragma unroll
            for (int nb = 0; nb < 2; nb++) {
                uint32_t addr = xh + 5120 + (uint32_t)((wn * 32 + nb * 16 + (lane & 15)) * 80
                                                       + kboff + (lane >> 4) * 16);
                uint32_t r0, r1, r2, r3;
                LDSM4(r0, r1, r2, r3, addr);
                bh[nb * 2][0] = r0; bh[nb * 2][1] = r2;
                bh[nb * 2 + 1][0] = r1; bh[nb * 2 + 1][1] = r3;
            }
#pragma unroll
            for (int mt = 0; mt < 2; mt++)
#pragma unroll
                for (int nt = 0; nt < 4; nt++)
                    MMA_FP16(c[mt][nt], a[mt], bh[nt]);
        }
    };

    // ---- pipelined mainloop ----
    ldgX(0);
    cpW(0, 0);
    CP_COMMIT();
    stX(0);
    for (int i = 0; i < 32; i++) {
        int buf = i & 1;
        CP_WAIT0();
        __syncthreads();
        if (i < 31) {
            ldgX((i + 1) * 32);
            cpW((i + 1) * 32, buf ^ 1);
            CP_COMMIT();
        }
        domma(buf);
        if (i < 31) stX(buf ^ 1);
    }
    __syncthreads();   // buffers now reusable as Ks/Vs

    // ---- epilogue: bias, stage K/V, 64-deep outer product, atomicAdd ----
    float* Ks = (float*)sm;               // [64][68]
    float* Vs = (float*)(sm + 17408);     // [64][68]
#pragma unroll
    for (int mt = 0; mt < 2; mt++) {
        int r = wm * 32 + mt * 16 + g;
#pragma unroll
        for (int nt = 0; nt < 4; nt++) {
            int nbase = wn * 32 + nt * 8;
            int which = nbase >> 6;              // 0 = K, 1 = V
            int nc    = (nbase & 63) + 2 * tig;
            const float* bias = which ? bv : bk;
            float* S = which ? Vs : Ks;
            float b0v = bias[nc];
            float b1v = bias[nc + 1];
            S[r * 68 + nc]           = c[mt][nt][0] + b0v;
            S[r * 68 + nc + 1]       = c[mt][nt][1] + b1v;
            S[(r + 8) * 68 + nc]     = c[mt][nt][2] + b0v;
            S[(r + 8) * 68 + nc + 1] = c[mt][nt][3] + b1v;
        }
    }
    __syncthreads();

    {
        const int i0 = (t >> 4) * 4;
        const int j0 = (t & 15) * 4;
        float acc[4][4];
#pragma unroll
        for (int i = 0; i < 4; i++)
#pragma unroll
            for (int j = 0; j < 4; j++) acc[i][j] = 0.f;
#pragma unroll 8
        for (int s = 0; s < 64; s++) {
            float4 kk = *(const float4*)&Ks[s * 68 + i0];
            float4 vv = *(const float4*)&Vs[s * 68 + j0];
            float a[4] = {kk.x, kk.y, kk.z, kk.w};
            float b2[4] = {vv.x, vv.y, vv.z, vv.w};
#pragma unroll
            for (int i = 0; i < 4; i++)
#pragma unroll
                for (int j = 0; j < 4; j++)
                    acc[i][j] += a[i] * b2[j];
        }
        float* Mb = g_M + (size_t)batch * HH * HH;
#pragma unroll
        for (int i = 0; i < 4; i++)
#pragma unroll
            for (int j = 0; j < 4; j++)
                atomicAdd(&Mb[(i0 + i) * HH + j0 + j], acc[i][j]);
    }
}

// ---------------------------------------------------------------------------
// wprime: W''_b = SCALE*(Wq @ M_b) -> fp16 transposed [b][n][k]; c_b = SCALE*bq@M_b
// grid (16, BB); block handles 64 e-rows. All accesses smem-staged/coalesced.
// ---------------------------------------------------------------------------
__global__ __launch_bounds__(256) void wprime_kernel(
    const float* __restrict__ Wq,
    const float* __restrict__ bq)
{
    __shared__ float Ms[64][65];
    __shared__ float Wqs[64][65];
    __shared__ unsigned short Wt[64][66];

    const int t  = threadIdx.x;
    const int b  = blockIdx.y;
    const int r0 = blockIdx.x * 64;

    // load M_b and Wq tile (both coalesced, 16 floats/thread each)
#pragma unroll
    for (int l = 0; l < 16; l++) {
        int f = t + l * 256;
        Ms[f >> 6][f & 63] = g_M[(size_t)b * HH * HH + f];
        Wqs[f >> 6][f & 63] = Wq[(size_t)(r0 + (f >> 6)) * HH + (f & 63)];
    }
    __syncthreads();

    const int i  = t >> 2;          // e-local row 0..63
    const int j0 = (t & 3) * 16;    // output cols j0..j0+15
    float acc[16];
#pragma unroll
    for (int j = 0; j < 16; j++) acc[j] = 0.f;
#pragma unroll 8
    for (int k = 0; k < 64; k++) {
        float w = Wqs[i][k];
#pragma unroll
        for (int j = 0; j < 16; j++)
            acc[j] += w * Ms[k][j0 + j];
    }
#pragma unroll
    for (int j = 0; j < 16; j++)
        Wt[j0 + j][i] = __half_as_ushort(__float2half_rn(acc[j] * SCALE));

    if (blockIdx.x == 0 && t < 64) {
        float a = 0.f;
#pragma unroll 8
        for (int k = 0; k < 64; k++)
            a += bq[k] * Ms[k][t];
        g_c[b * HH + t] = a * SCALE;
    }
    __syncthreads();

    // coalesced store of transposed fp16 plane
#pragma unroll
    for (int l = 0; l < 8; l++) {
        int f = t + l * 256;              // 0..2047
        int n = f >> 5;                   // 0..63
        int e2 = (f & 31) * 2;
        uint32_t v = (uint32_t)Wt[n][e2] | ((uint32_t)Wt[n][e2 + 1] << 16);
        *(uint32_t*)(g_Wp + (size_t)b * HH * EE + (size_t)n * EE + r0 + e2) = v;
    }
}

// ---------------------------------------------------------------------------
// out GEMM: out = X @ W''_b + c_b. M=16384, N=64, K=1024. grid = 128 blocks
// of 128 rows. 8 warps (4M x 2N), warp tile 32x32, BK=32, double-buffered.
// ---------------------------------------------------------------------------
#define OUT_BUFS 15360
#define OUT_SMEM (2 * OUT_BUFS)

__global__ __launch_bounds__(256) void out_mma_kernel(
    const float* __restrict__ X,
    float* __restrict__ out)
{
    extern __shared__ __align__(16) char sm[];
    const uint32_t sb = smem_u32(sm);
    const int t    = threadIdx.x;
    const int warp = t >> 5;
    const int lane = t & 31;
    const int g    = lane >> 2;
    const int tig  = lane & 3;
    const int wm   = warp >> 1;      // 0..3
    const int wn   = warp & 1;       // 0..1
    const int m0   = blockIdx.x * 128;
    const int batch = m0 >> 12;

    const float4* X4 = (const float4*)X;
    const __half* WHp = g_Wp + (size_t)batch * HH * EE;

    float c[2][4][4];
#pragma unroll
    for (int mt = 0; mt < 2; mt++)
#pragma unroll
        for (int nt = 0; nt < 4; nt++)
#pragma unroll
            for (int j = 0; j < 4; j++) c[mt][nt][j] = 0.f;

    float4 xr[4];
    const int xrow = t >> 3;         // 0..31 (4 rows per thread, stride 32)
    const int xc4  = t & 7;

    auto ldgX = [&](int k0) {
#pragma unroll
        for (int j = 0; j < 4; j++)
            xr[j] = X4[(size_t)(m0 + xrow + j * 32) * (EE / 4) + (k0 >> 2) + xc4];
    };
    auto stX = [&](int buf) {
        char* xh = sm + buf * OUT_BUFS;
#pragma unroll
        for (int j = 0; j < 4; j++) {
            __half2 p0 = __floats2half2_rn(xr[j].x, xr[j].y);
            __half2 p1 = __floats2half2_rn(xr[j].z, xr[j].w);
            int off = (xrow + j * 32) * 80 + xc4 * 8;
            *(uint2*)(xh + off) = make_uint2(*(uint32_t*)&p0, *(uint32_t*)&p1);
        }
    };
    auto cpW = [&](int k0, int buf) {
        uint32_t wbase = sb + buf * OUT_BUFS + 10240;
        int row = t >> 2;              // 0..63
        int q = t & 3;
        const __half* src = WHp + (size_t)row * EE + k0 + q * 8;
        uint32_t dst = wbase + row * 80 + q * 16;
        CP_ASYNC16(dst, src);
    };
    auto domma = [&](int buf) {
        uint32_t xh = sb + buf * OUT_BUFS;
#pragma unroll
        for (int ks = 0; ks < 2; ks++) {
            const int kboff = ks * 32;
            uint32_t a[2][4], bh[4][2];
#pragma unroll
            for (int mt = 0; mt < 2; mt++) {
                uint32_t addr = xh + (uint32_t)((wm * 32 + mt * 16 + (lane & 15)) * 80
                                                + kboff + (lane >> 4) * 16);
                LDSM4(a[mt][0], a[mt][1], a[mt][2], a[mt][3], addr);
            }
#pragma unroll
            for (int nb = 0; nb < 2; nb++) {
                uint32_t addr = xh + 10240 + (uint32_t)((wn * 32 + nb * 16 + (lane & 15)) * 80
                                                        + kboff + (lane >> 4) * 16);
                uint32_t r0, r1, r2, r3;
                LDSM4(r0, r1, r2, r3, addr);
                bh[nb * 2][0] = r0; bh[nb * 2][1] = r2;
                bh[nb * 2 + 1][0] = r1; bh[nb * 2 + 1][1] = r3;
            }
#pragma unroll
            for (int mt = 0; mt < 2; mt++)
#pragma unroll
                for (int nt = 0; nt < 4; nt++)
                    MMA_FP16(c[mt][nt], a[mt], bh[nt]);
        }
    };

    ldgX(0);
    cpW(0, 0);
    CP_COMMIT();
    stX(0);
    for (int i = 0; i < 32; i++) {
        int buf = i & 1;
        CP_WAIT0();
        __syncthreads();
        if (i < 31) {
            ldgX((i + 1) * 32);
            cpW((i + 1) * 32, buf ^ 1);
            CP_COMMIT();
        }
        domma(buf);
        if (i < 31) stX(buf ^ 1);
    }

    // ---- epilogue: + c_b, store fp32 ----
    const float* cv = g_c + batch * HH;
#pragma unroll
    for (int mt = 0; mt < 2; mt++) {
        int r0 = m0 + wm * 32 + mt * 16 + g;
#pragma unroll
        for (int nt = 0; nt < 4; nt++) {
            int n = wn * 32 + nt * 8 + 2 * tig;
            float c0 = cv[n];
            float c1 = cv[n + 1];
            float2 o0 = {c[mt][nt][0] + c0, c[mt][nt][1] + c1};
            float2 o1 = {c[mt][nt][2] + c0, c[mt][nt][3] + c1};
            *(float2*)&out[(size_t)r0 * HH + n] = o0;
            *(float2*)&out[(size_t)(r0 + 8) * HH + n] = o1;
        }
    }
}

// ---------------------------------------------------------------------------
// Launch
// ---------------------------------------------------------------------------
extern "C" void kernel_launch(void* const* d_in, const int* in_sizes, int n_in,
                              void* d_out, int out_size)
{
    const float* idx = (const float*)d_in[0];
    const float* Wq  = (const float*)d_in[1];
    const float* bq  = (const float*)d_in[2];
    const float* Wk  = (const float*)d_in[3];
    const float* bk  = (const float*)d_in[4];
    const float* Wv  = (const float*)d_in[5];
    const float* bv  = (const float*)d_in[6];
    float* out = (float*)d_out;

    static bool attr_set = false;
    if (!attr_set) {
        cudaFuncSetAttribute(kv_mma_kernel,
                             cudaFuncAttributeMaxDynamicSharedMemorySize, KV_SMEM);
        cudaFuncSetAttribute(out_mma_kernel,
                             cudaFuncAttributeMaxDynamicSharedMemorySize, OUT_SMEM);
        attr_set = true;
    }

    prep_kernel<<<(128 * EE + 255) / 256, 256>>>(Wk, Wv);

    kv_mma_kernel<<<BT / 64, 256, KV_SMEM>>>(idx, bk, bv);

    wprime_kernel<<<dim3(16, BB), 256>>>(Wq, bq);

    out_mma_kernel<<<BT / 128, 256, OUT_SMEM>>>(idx, out);
}

// round 12
// speedup vs baseline: 1.3903x; 1.3903x over previous
#include <cuda_runtime.h>
#include <cuda_fp16.h>
#include <cstdint>

// Problem dims (fixed)
#define BB 4
#define TT 4096
#define EE 1024
#define HH 64
#define BT (BB * TT)          // 16384 rows
#define SCALE 0.03125f        // E^-0.5

// Scratch (device globals)
__device__ float g_Q[BT * HH];
__device__ float g_M[BB * HH * HH];
__device__ __half g_WT[192 * EE];   // [n][k]; n: q 0-63, k 64-127, v 128-191

// ---------------------------------------------------------------------------
// PTX helpers (baseline PTX, valid under compute_103)
// ---------------------------------------------------------------------------
#define MMA_FP16(c, a, b)                                                     \
    asm volatile(                                                             \
        "mma.sync.aligned.m16n8k16.row.col.f32.f16.f16.f32 "                  \
        "{%0,%1,%2,%3}, {%4,%5,%6,%7}, {%8,%9}, {%0,%1,%2,%3};\n"             \
        : "+f"(c[0]), "+f"(c[1]), "+f"(c[2]), "+f"(c[3])                      \
        : "r"(a[0]), "r"(a[1]), "r"(a[2]), "r"(a[3]), "r"(b[0]), "r"(b[1]))

#define LDSM4(r0, r1, r2, r3, addr)                                           \
    asm volatile("ldmatrix.sync.aligned.m8n8.x4.shared.b16 {%0,%1,%2,%3}, [%4];" \
        : "=r"(r0), "=r"(r1), "=r"(r2), "=r"(r3) : "r"(addr))

#define CP_ASYNC16(dst, src) \
    asm volatile("cp.async.cg.shared.global [%0], [%1], 16;" :: "r"(dst), "l"(src))
#define CP_COMMIT() asm volatile("cp.async.commit_group;")
#define CP_WAIT0()  asm volatile("cp.async.wait_group 0;")

__device__ __forceinline__ uint32_t smem_u32(const void* p) {
    uint32_t a;
    asm("{ .reg .u64 t; cvta.to.shared.u64 t, %1; cvt.u32.u64 %0, t; }" : "=r"(a) : "l"(p));
    return a;
}

// ---------------------------------------------------------------------------
// Prep: zero g_M + convert Wq|Wk|Wv (fp32 [k][n]) -> fp16 transposed [n][k],
// smem tile transpose so BOTH the read and the write are coalesced.
// grid = 48 transpose blocks (3 matrices x 16 k-tiles) + 64 zero-M blocks.
// ---------------------------------------------------------------------------
__global__ __launch_bounds__(256) void prep_kernel(
    const float* __restrict__ Wq,
    const float* __restrict__ Wk,
    const float* __restrict__ Wv)
{
    const int t = threadIdx.x;
    if (blockIdx.x >= 48) {
        int i = (blockIdx.x - 48) * 256 + t;
        g_M[i] = 0.f;
        return;
    }
    __shared__ float Ws[64][65];
    const int m  = blockIdx.x / 16;      // 0=Wq, 1=Wk, 2=Wv
    const int k0 = (blockIdx.x % 16) * 64;
    const float* W = (m == 0) ? Wq : (m == 1) ? Wk : Wv;

#pragma unroll
    for (int l = 0; l < 16; l++) {
        int f = t + l * 256;             // 0..4095
        int row = f >> 6;                // k-local 0..63
        int col = f & 63;                // n
        Ws[row][col] = W[(size_t)(k0 + row) * HH + col];
    }
    __syncthreads();
#pragma unroll
    for (int l = 0; l < 16; l++) {
        int f = t + l * 256;
        int n  = f >> 6;                 // 0..63
        int kk = f & 63;                 // k-local, consecutive per thread
        g_WT[(size_t)(m * 64 + n) * EE + k0 + kk] = __float2half_rn(Ws[kk][n]);
    }
}

// ---------------------------------------------------------------------------
// Fused QKV + K^T V: one block = 64 rows x 192 cols (Q|K|V), single fp16 pass.
// Epilogue: Q -> g_Q (bias); K,V staged to smem, 64-deep outer product
// atomicAdd into g_M. grid = BT/64 = 256 blocks, 256 threads = 8 warps
// (2M x 4N), warp tile 32(M) x 48(N). BK=32.
//
// Dynamic smem per buffer (stride 20480B): Xh 64x80B @0, Wh 192x80B @5120.
// Two buffers = 40960 B (< default 48K). Epilogue reuses pool:
// Ks[64][68] @0 (17408) + Vs[64][68] @17408 = 34816 B.
// ---------------------------------------------------------------------------
#define BUFS 20480
#define QKV_SMEM (2 * BUFS)

__global__ __launch_bounds__(256) void qkv_mma_kernel(
    const float* __restrict__ X,
    const float* __restrict__ bq,
    const float* __restrict__ bkk,
    const float* __restrict__ bv)
{
    extern __shared__ __align__(16) char sm[];
    const uint32_t sb = smem_u32(sm);
    const int t    = threadIdx.x;
    const int warp = t >> 5;
    const int lane = t & 31;
    const int g    = lane >> 2;
    const int tig  = lane & 3;
    const int wm   = warp >> 2;      // 0..1 -> m offset 32*wm
    const int wn   = warp & 3;       // 0..3 -> n offset 48*wn
    const int m0   = blockIdx.x * 64;
    const int batch = m0 >> 12;      // 4096 rows per batch

    const float4* X4 = (const float4*)X;

    float c[2][6][4];
#pragma unroll
    for (int mt = 0; mt < 2; mt++)
#pragma unroll
        for (int nt = 0; nt < 6; nt++)
#pragma unroll
            for (int j = 0; j < 4; j++) c[mt][nt][j] = 0.f;

    float4 xr[2];
    const int xrow = t >> 2;         // 0..63
    const int xc4  = (t & 3) * 2;    // float4 chunks xc4, xc4+1

    auto ldgX = [&](int k0) {
#pragma unroll
        for (int j = 0; j < 2; j++)
            xr[j] = X4[(size_t)(m0 + xrow) * (EE / 4) + (k0 >> 2) + xc4 + j];
    };
    auto stX = [&](int buf) {
        char* xh = sm + buf * BUFS;
#pragma unroll
        for (int j = 0; j < 2; j++) {
            __half2 p0 = __floats2half2_rn(xr[j].x, xr[j].y);
            __half2 p1 = __floats2half2_rn(xr[j].z, xr[j].w);
            int off = xrow * 80 + (xc4 + j) * 8;
            *(uint2*)(xh + off) = make_uint2(*(uint32_t*)&p0, *(uint32_t*)&p1);
        }
    };
    // W tile: 192 rows x 32 cols fp16 = 768 x 16B, 3/thread
    auto cpW = [&](int k0, int buf) {
        uint32_t wbase = sb + buf * BUFS + 5120;
#pragma unroll
        for (int j = 0; j < 3; j++) {
            int cc = t + j * 256;          // 0..767
            int row = cc >> 2;             // 0..191
            int q = cc & 3;
            const __half* src = g_WT + (size_t)row * EE + k0 + q * 8;
            uint32_t dst = wbase + row * 80 + q * 16;
            CP_ASYNC16(dst, src);
        }
    };
    auto domma = [&](int buf) {
        uint32_t xh = sb + buf * BUFS;
#pragma unroll
        for (int ks = 0; ks < 2; ks++) {
            const int kboff = ks * 32;
            uint32_t a[2][4], bh[6][2];
#pragma unroll
            for (int mt = 0; mt < 2; mt++) {
                uint32_t addr = xh + (uint32_t)((wm * 32 + mt * 16 + (lane & 15)) * 80
                                                + kboff + (lane >> 4) * 16);
                LDSM4(a[mt][0], a[mt][1], a[mt][2], a[mt][3], addr);
            }
#pragma unroll
            for (int nb = 0; nb < 3; nb++) {
                uint32_t addr = xh + 5120 + (uint32_t)((wn * 48 + nb * 16 + (lane & 15)) * 80
                                                       + kboff + (lane >> 4) * 16);
                uint32_t r0, r1, r2, r3;
                LDSM4(r0, r1, r2, r3, addr);
                bh[nb * 2][0] = r0; bh[nb * 2][1] = r2;
                bh[nb * 2 + 1][0] = r1; bh[nb * 2 + 1][1] = r3;
            }
#pragma unroll
            for (int mt = 0; mt < 2; mt++)
#pragma unroll
                for (int nt = 0; nt < 6; nt++)
                    MMA_FP16(c[mt][nt], a[mt], bh[nt]);
        }
    };

    // ---- pipelined mainloop: 32 tiles of BK=32 ----
    ldgX(0);
    cpW(0, 0);
    CP_COMMIT();
    stX(0);
    for (int i = 0; i < 32; i++) {
        int buf = i & 1;
        CP_WAIT0();
        __syncthreads();
        if (i < 31) {
            ldgX((i + 1) * 32);
            cpW((i + 1) * 32, buf ^ 1);
            CP_COMMIT();
        }
        domma(buf);
        if (i < 31) stX(buf ^ 1);
    }
    __syncthreads();   // all ldsm reads done; smem reusable for K/V staging

    // ---- epilogue: Q -> g_Q; K,V -> smem; K^T V -> atomicAdd g_M ----
    float* Ks = (float*)sm;               // [64][68]
    float* Vs = (float*)(sm + 17408);     // [64][68]
#pragma unroll
    for (int mt = 0; mt < 2; mt++) {
        int r = wm * 32 + mt * 16 + g;
#pragma unroll
        for (int nt = 0; nt < 6; nt++) {
            int nbase = wn * 48 + nt * 8;       // 8-aligned
            int which = nbase >> 6;              // 0=Q, 1=K, 2=V
            int nc    = (nbase & 63) + 2 * tig;
            if (which == 0) {
                float b0v = bq[nc];
                float b1v = bq[nc + 1];
                float2 o0 = {c[mt][nt][0] + b0v, c[mt][nt][1] + b1v};
                float2 o1 = {c[mt][nt][2] + b0v, c[mt][nt][3] + b1v};
                *(float2*)&g_Q[(size_t)(m0 + r) * HH + nc] = o0;
                *(float2*)&g_Q[(size_t)(m0 + r + 8) * HH + nc] = o1;
            } else {
                const float* bias = (which == 1) ? bkk : bv;
                float* S = (which == 1) ? Ks : Vs;
                float b0v = bias[nc];
                float b1v = bias[nc + 1];
                S[r * 68 + nc]           = c[mt][nt][0] + b0v;
                S[r * 68 + nc + 1]       = c[mt][nt][1] + b1v;
                S[(r + 8) * 68 + nc]     = c[mt][nt][2] + b0v;
                S[(r + 8) * 68 + nc + 1] = c[mt][nt][3] + b1v;
            }
        }
    }
    __syncthreads();

    {
        const int i0 = (t >> 4) * 4;    // h1
        const int j0 = (t & 15) * 4;    // h2
        float acc[4][4];
#pragma unroll
        for (int i = 0; i < 4; i++)
#pragma unroll
            for (int j = 0; j < 4; j++) acc[i][j] = 0.f;
#pragma unroll 8
        for (int s = 0; s < 64; s++) {
            float4 kk = *(const float4*)&Ks[s * 68 + i0];
            float4 vv = *(const float4*)&Vs[s * 68 + j0];
            float a[4] = {kk.x, kk.y, kk.z, kk.w};
            float b2[4] = {vv.x, vv.y, vv.z, vv.w};
#pragma unroll
            for (int i = 0; i < 4; i++)
#pragma unroll
                for (int j = 0; j < 4; j++)
                    acc[i][j] += a[i] * b2[j];
        }
        float* Mb = g_M + (size_t)batch * HH * HH;
#pragma unroll
        for (int i = 0; i < 4; i++)
#pragma unroll
            for (int j = 0; j < 4; j++)
                atomicAdd(&Mb[(i0 + i) * HH + j0 + j], acc[i][j]);
    }
}

// ---------------------------------------------------------------------------
// out[b] = SCALE * Q[b] @ M[b].  grid = BT/64 = 256 blocks.
// ---------------------------------------------------------------------------
__global__ __launch_bounds__(256) void out_kernel(float* __restrict__ out)
{
    __shared__ float Ms[64][68];
    __shared__ float Qs[64][68];

    const int t    = threadIdx.x;
    const int tx   = t & 15;
    const int ty   = t >> 4;
    const int row0 = blockIdx.x * 64;
    const int b    = row0 / TT;

    const float4* Q4 = (const float4*)(g_Q + (size_t)row0 * HH);
    const float4* M4 = (const float4*)(g_M + (size_t)b * HH * HH);

#pragma unroll
    for (int l = 0; l < 4; l++) {
        int f   = t + l * 256;
        int row = f >> 4;
        int c4  = f & 15;
        float4 qv = Q4[(size_t)row * 16 + c4];
        float4 mv = M4[(size_t)row * 16 + c4];
        *(float4*)&Qs[row][c4 * 4] = qv;
        *(float4*)&Ms[row][c4 * 4] = mv;
    }
    __syncthreads();

    float acc[4][4];
#pragma unroll
    for (int i = 0; i < 4; i++)
#pragma unroll
        for (int j = 0; j < 4; j++) acc[i][j] = 0.f;

#pragma unroll 4
    for (int k0 = 0; k0 < 64; k0 += 4) {
        float4 q4[4];
#pragma unroll
        for (int i = 0; i < 4; i++)
            q4[i] = *(const float4*)&Qs[ty * 4 + i][k0];
#pragma unroll
        for (int kk = 0; kk < 4; kk++) {
            float4 m4 = *(const float4*)&Ms[k0 + kk][tx * 4];
            float m[4] = {m4.x, m4.y, m4.z, m4.w};
#pragma unroll
            for (int i = 0; i < 4; i++) {
                float qv = (kk == 0) ? q4[i].x : (kk == 1) ? q4[i].y
                         : (kk == 2) ? q4[i].z : q4[i].w;
#pragma unroll
                for (int j = 0; j < 4; j++)
                    acc[i][j] += qv * m[j];
            }
        }
    }

#pragma unroll
    for (int i = 0; i < 4; i++) {
        int r = row0 + ty * 4 + i;
        float4 o;
        o.x = acc[i][0] * SCALE;
        o.y = acc[i][1] * SCALE;
        o.z = acc[i][2] * SCALE;
        o.w = acc[i][3] * SCALE;
        *(float4*)&out[(size_t)r * HH + tx * 4] = o;
    }
}

// ---------------------------------------------------------------------------
// Launch
// ---------------------------------------------------------------------------
extern "C" void kernel_launch(void* const* d_in, const int* in_sizes, int n_in,
                              void* d_out, int out_size)
{
    const float* idx = (const float*)d_in[0];
    const float* Wq  = (const float*)d_in[1];
    const float* bq  = (const float*)d_in[2];
    const float* Wk  = (const float*)d_in[3];
    const float* bk  = (const float*)d_in[4];
    const float* Wv  = (const float*)d_in[5];
    const float* bv  = (const float*)d_in[6];
    float* out = (float*)d_out;

    prep_kernel<<<48 + (BB * HH * HH) / 256, 256>>>(Wq, Wk, Wv);

    qkv_mma_kernel<<<BT / 64, 256, QKV_SMEM>>>(idx, bq, bk, bv);

    out_kernel<<<BT / 64, 256>>>(out);
}